// round 7
// baseline (speedup 1.0000x reference)
#include <cuda_runtime.h>

#define TT   2048
#define HB   128
#define NL   3
#define GCTA 32
#define NJ   4
#define NR   16

// Layer 0: K = 8(pad) + 128 = 136 ; layers 1,2: K = 256
#define WOFF0 0
#define WOFF1 (GCTA*NR*136)
#define WOFF2 (WOFF1 + GCTA*NR*256)
#define WTOT  (WOFF2 + GCTA*NR*256)

// h history: layer l, slot s (= h after step s-1; slot 0 = zeros), [hidden j][batch b]
__device__ float g_H[(size_t)NL * (TT + 1) * HB * HB];
__device__ float g_xT[TT * 8 * HB];
__device__ float g_Wp[WTOT];
__device__ float g_bias[NL * GCTA * NR];
__device__ int   g_flags[NL * TT];

typedef unsigned long long ull;

__device__ __forceinline__ ull pk2(float lo, float hi) {
    ull r; asm("mov.b64 %0,{%1,%2};" : "=l"(r) : "f"(lo), "f"(hi)); return r;
}
__device__ __forceinline__ void upk2(ull v, float& lo, float& hi) {
    asm("mov.b64 {%0,%1},%2;" : "=f"(lo), "=f"(hi) : "l"(v));
}
__device__ __forceinline__ ull ffma2(ull a, ull b, ull c) {
    ull d; asm("fma.rn.f32x2 %0,%1,%2,%3;" : "=l"(d) : "l"(a), "l"(b), "l"(c));
    return d;
}
__device__ __forceinline__ int ldacq(const int* p) {
    int v; asm volatile("ld.acquire.gpu.global.b32 %0,[%1];" : "=r"(v) : "l"(p) : "memory");
    return v;
}
__device__ __forceinline__ void red_release(int* p) {
    asm volatile("red.release.gpu.global.add.s32 [%0],1;" :: "l"(p) : "memory");
}
__device__ __forceinline__ float sigf(float x) {
    return __fdividef(1.0f, 1.0f + __expf(-x));
}
__device__ __forceinline__ float tanhf_fast(float x) {
    return __fdividef(2.0f, 1.0f + __expf(-2.0f * x)) - 1.0f;
}

// ---- pack weights/bias: row r=q*4+jj <-> gate row q*128+(g*4+jj); cols [0,KA)=W_ih (l0 pad 6->8), [KA,KP)=W_hh
__global__ void pack_kernel(
    const float* __restrict__ Wih0, const float* __restrict__ Whh0,
    const float* __restrict__ bih0, const float* __restrict__ bhh0,
    const float* __restrict__ Wih1, const float* __restrict__ Whh1,
    const float* __restrict__ bih1, const float* __restrict__ bhh1,
    const float* __restrict__ Wih2, const float* __restrict__ Whh2,
    const float* __restrict__ bih2, const float* __restrict__ bhh2)
{
    int blk = blockIdx.x;
    int l = blk / GCTA, g = blk % GCTA;
    const float* Wih = (l == 0) ? Wih0 : ((l == 1) ? Wih1 : Wih2);
    const float* Whh = (l == 0) ? Whh0 : ((l == 1) ? Whh1 : Whh2);
    const float* bih = (l == 0) ? bih0 : ((l == 1) ? bih1 : bih2);
    const float* bhh = (l == 0) ? bhh0 : ((l == 1) ? bhh1 : bhh2);

    int KA = (l == 0) ? 8 : 128;
    int KP = KA + 128;
    int base = ((l == 0) ? WOFF0 : ((l == 1) ? WOFF1 : WOFF2)) + g * NR * KP;

    for (int idx = threadIdx.x; idx < NR * KP; idx += blockDim.x) {
        int r = idx / KP, k = idx % KP;
        int q = r >> 2, jj = r & 3;
        int R = q * 128 + (g * NJ + jj);
        float v;
        if (k < KA) v = (l == 0) ? ((k < 6) ? Wih[R * 6 + k] : 0.0f)
                                 : Wih[R * 128 + k];
        else        v = Whh[R * 128 + (k - KA)];
        g_Wp[base + idx] = v;
    }
    if (threadIdx.x < NR) {
        int r = threadIdx.x, q = r >> 2, jj = r & 3;
        int R = q * 128 + (g * NJ + jj);
        g_bias[(l * GCTA + g) * NR + r] = bih[R] + bhh[R];
    }
}

// ---- transpose x -> xT[t][i pad 8][b]; zero h slot 0 per layer; zero flags
__global__ void prep_kernel(const float* __restrict__ x)
{
    int blk = blockIdx.x, tid = threadIdx.x;
    if (blk < TT) {
        int t = blk;
        #pragma unroll
        for (int i = 0; i < 8; i++) {
            float v = (i < 6) ? x[(size_t)tid * (TT * 6) + t * 6 + i] : 0.0f;
            g_xT[(t * 8 + i) * HB + tid] = v;
        }
    } else if (blk < TT + NL) {
        size_t base = (size_t)(blk - TT) * (TT + 1) * HB * HB;
        for (int i = tid; i < HB * HB; i += 128) g_H[base + i] = 0.0f;
    } else {
        for (int i = tid; i < NL * TT; i += 128) g_flags[i] = 0;
    }
}

// ---- GEMM slice over packed cols [S,E), source element for col k = src[(k-DELTA)*HB + b]
template<int KP, int S, int E, int DELTA>
__device__ __forceinline__ void gemm4(const float* __restrict__ src,
                                      const float* __restrict__ Wsm,
                                      int b, ull* acc)
{
    #pragma unroll 4
    for (int k = S; k < E; k += 4) {
        float a0 = __ldcg(src + (k - DELTA + 0) * HB + b);
        float a1 = __ldcg(src + (k - DELTA + 1) * HB + b);
        float a2 = __ldcg(src + (k - DELTA + 2) * HB + b);
        float a3 = __ldcg(src + (k - DELTA + 3) * HB + b);
        ull h01 = pk2(a0, a1), h23 = pk2(a2, a3);
        const float* wrow = Wsm + k;
        #pragma unroll
        for (int r = 0; r < NR; r++) {
            ulonglong2 w = *(const ulonglong2*)(wrow + r * KP); // LDS.128 bcast, imm offset
            acc[r] = ffma2(w.x, h01, acc[r]);
            acc[r] = ffma2(w.y, h23, acc[r]);
        }
    }
}

// ---- 2-col slice (layer 0 input part: 8 cols / 4 kq)
template<int KP, int S>
__device__ __forceinline__ void gemm2(const float* __restrict__ src,
                                      const float* __restrict__ Wsm,
                                      int b, ull* acc)
{
    float a0 = __ldcg(src + (S + 0) * HB + b);
    float a1 = __ldcg(src + (S + 1) * HB + b);
    ull h01 = pk2(a0, a1);
    #pragma unroll
    for (int r = 0; r < NR; r++) {
        ull w = *(const ull*)(Wsm + S + r * KP);   // LDS.64 bcast
        acc[r] = ffma2(w, h01, acc[r]);
    }
}

// ---- per-layer persistent body, 512 threads.
// GEMM: warp = kq*4+bg (kq = K-slice, bg = batch group, lane = batch col).
// Epilogue: thread owns (jj = tid>>7, be = tid&127); carries c state.
template<int L>
__device__ __forceinline__ void lstm_run(int g, float* Wsm, float* RD, float* bsm)
{
    constexpr int KA = (L == 0) ? 8 : 128;
    constexpr int KP = KA + 128;
    constexpr int WOFF = (L == 0) ? WOFF0 : ((L == 1) ? WOFF1 : WOFF2);

    const int tid  = threadIdx.x;
    const int lane = tid & 31;
    const int warp = tid >> 5;
    const int bg   = warp & 3;
    const int kq   = warp >> 2;
    const int b    = bg * 32 + lane;
    const int jj   = tid >> 7;
    const int be   = tid & 127;
    const int jrow = g * NJ + jj;

    const int wbase = WOFF + g * NR * KP;
    for (int i = tid; i < NR * KP; i += 512) Wsm[i] = g_Wp[wbase + i];
    if (tid < NR) bsm[tid] = g_bias[(L * GCTA + g) * NR + tid];
    __syncthreads();

    float c = 0.0f;

    for (int t = 0; t < TT; t++) {
        // ---- phase A: input / below-layer contribution (own-h flag NOT yet needed)
        if (L > 0) {
            if (tid == 0) {
                const int* f = &g_flags[(L - 1) * TT + t];
                while (ldacq(f) < GCTA) {}
            }
            __syncthreads();
        }
        const float* SA = (L == 0)
            ? (g_xT + (size_t)t * 8 * HB)
            : (g_H + (size_t)((L - 1) * (TT + 1) + t + 1) * HB * HB);

        ull acc[NR];
        #pragma unroll
        for (int r = 0; r < NR; r++) acc[r] = 0ULL;

        if constexpr (L == 0) {
            switch (kq) {
            case 0:  gemm2<KP, 0>(SA, Wsm, b, acc); break;
            case 1:  gemm2<KP, 2>(SA, Wsm, b, acc); break;
            case 2:  gemm2<KP, 4>(SA, Wsm, b, acc); break;
            default: gemm2<KP, 6>(SA, Wsm, b, acc); break;
            }
        } else {
            switch (kq) {
            case 0:  gemm4<KP,  0,  32, 0>(SA, Wsm, b, acc); break;
            case 1:  gemm4<KP, 32,  64, 0>(SA, Wsm, b, acc); break;
            case 2:  gemm4<KP, 64,  96, 0>(SA, Wsm, b, acc); break;
            default: gemm4<KP, 96, 128, 0>(SA, Wsm, b, acc); break;
            }
        }

        // ---- phase B: own h(t-1) (sync latency now hidden behind phase A)
        if (tid == 0 && t > 0) {
            const int* f = &g_flags[L * TT + t - 1];
            while (ldacq(f) < GCTA) {}
        }
        __syncthreads();
        const float* SB = g_H + (size_t)(L * (TT + 1) + t) * HB * HB;

        switch (kq) {
        case 0:  gemm4<KP, KA +  0, KA +  32, KA>(SB, Wsm, b, acc); break;
        case 1:  gemm4<KP, KA + 32, KA +  64, KA>(SB, Wsm, b, acc); break;
        case 2:  gemm4<KP, KA + 64, KA +  96, KA>(SB, Wsm, b, acc); break;
        default: gemm4<KP, KA + 96, KA + 128, KA>(SB, Wsm, b, acc); break;
        }

        #pragma unroll
        for (int r = 0; r < NR; r++) {
            float lo, hi; upk2(acc[r], lo, hi);
            RD[(kq * NR + r) * HB + b] = lo + hi;
        }
        __syncthreads();

        // ---- epilogue: every thread one (jj, be)
        float v0 = bsm[0 * 4 + jj], v1 = bsm[1 * 4 + jj];
        float v2 = bsm[2 * 4 + jj], v3 = bsm[3 * 4 + jj];
        #pragma unroll
        for (int q2 = 0; q2 < 4; q2++) {
            v0 += RD[(q2 * NR + 0 * 4 + jj) * HB + be];
            v1 += RD[(q2 * NR + 1 * 4 + jj) * HB + be];
            v2 += RD[(q2 * NR + 2 * 4 + jj) * HB + be];
            v3 += RD[(q2 * NR + 3 * 4 + jj) * HB + be];
        }
        float iv = sigf(v0);
        float fv = sigf(v1);
        float gv = tanhf_fast(v2);
        float ov = sigf(v3);
        c = fv * c + iv * gv;
        float* Hout = g_H + (size_t)(L * (TT + 1) + t + 1) * HB * HB;
        __stcg(Hout + jrow * HB + be, ov * tanhf_fast(c));

        __syncthreads();   // all h stores done before release
        if (tid == 0) {
            asm volatile("fence.acq_rel.gpu;" ::: "memory");
            red_release(&g_flags[L * TT + t]);
        }
    }
}

__global__ void __launch_bounds__(512, 1) lstm_kernel()
{
    extern __shared__ float sm[];
    float* Wsm = sm;                       // NR*256 floats (16 KB)
    float* RD  = sm + NR * 256;            // 4*NR*HB floats (32 KB)
    float* bsm = RD + 4 * NR * HB;         // NR floats

    const int blk = blockIdx.x;
    const int l = blk >> 5, g = blk & 31;
    if (l == 0)      lstm_run<0>(g, Wsm, RD, bsm);
    else if (l == 1) lstm_run<1>(g, Wsm, RD, bsm);
    else             lstm_run<2>(g, Wsm, RD, bsm);
}

// ---- head: out[b] = h2[T-1][:,b] . W_out + b_out
__global__ void head_kernel(const float* __restrict__ W_out,
                            const float* __restrict__ b_out,
                            float* __restrict__ out)
{
    int b = threadIdx.x;
    const float* h = g_H + (size_t)(2 * (TT + 1) + TT) * HB * HB;
    float s = b_out[0];
    #pragma unroll 8
    for (int j = 0; j < HB; j++) s += h[j * HB + b] * W_out[j];
    out[b] = s;
}

extern "C" void kernel_launch(void* const* d_in, const int* in_sizes, int n_in,
                              void* d_out, int out_size)
{
    (void)in_sizes; (void)n_in; (void)out_size;
    const float* x = (const float*)d_in[0];

    const int SMEM_DYN = (NR * 256 + 4 * NR * HB + NR) * 4;   // 49,216 B
    cudaFuncSetAttribute(lstm_kernel,
                         cudaFuncAttributeMaxDynamicSharedMemorySize, SMEM_DYN);

    pack_kernel<<<NL * GCTA, 256>>>(
        (const float*)d_in[1], (const float*)d_in[2],
        (const float*)d_in[3], (const float*)d_in[4],
        (const float*)d_in[5], (const float*)d_in[6],
        (const float*)d_in[7], (const float*)d_in[8],
        (const float*)d_in[9], (const float*)d_in[10],
        (const float*)d_in[11], (const float*)d_in[12]);
    prep_kernel<<<TT + NL + 1, 128>>>(x);
    lstm_kernel<<<NL * GCTA, 512, SMEM_DYN>>>();
    head_kernel<<<1, 128>>>((const float*)d_in[13], (const float*)d_in[14],
                            (float*)d_out);
}

// round 8
// speedup vs baseline: 1.2924x; 1.2924x over previous
#include <cuda_runtime.h>

#define TT   2048
#define HB   128
#define NL   3
#define GCTA 32
#define NJ   4
#define NR   16

// Layer 0: K = 8(pad) + 128 = 136 ; layers 1,2: K = 256
#define WOFF0 0
#define WOFF1 (GCTA*NR*136)
#define WOFF2 (WOFF1 + GCTA*NR*256)
#define WTOT  (WOFF2 + GCTA*NR*256)

// h history: layer l, slot s (= h after step s-1; slot 0 = zeros), [hidden j][batch b]
__device__ float g_H[(size_t)NL * (TT + 1) * HB * HB];
__device__ float g_xT[TT * 8 * HB];
__device__ float g_Wp[WTOT];
__device__ float g_bias[NL * GCTA * NR];
__device__ int   g_flags[NL * TT];

typedef unsigned long long ull;

__device__ __forceinline__ ull pk2(float lo, float hi) {
    ull r; asm("mov.b64 %0,{%1,%2};" : "=l"(r) : "f"(lo), "f"(hi)); return r;
}
__device__ __forceinline__ void upk2(ull v, float& lo, float& hi) {
    asm("mov.b64 {%0,%1},%2;" : "=f"(lo), "=f"(hi) : "l"(v));
}
__device__ __forceinline__ ull ffma2(ull a, ull b, ull c) {
    ull d; asm("fma.rn.f32x2 %0,%1,%2,%3;" : "=l"(d) : "l"(a), "l"(b), "l"(c));
    return d;
}
__device__ __forceinline__ int ldacq(const int* p) {
    int v; asm volatile("ld.acquire.gpu.global.b32 %0,[%1];" : "=r"(v) : "l"(p) : "memory");
    return v;
}
__device__ __forceinline__ void red_release(int* p) {
    asm volatile("red.release.gpu.global.add.s32 [%0],1;" :: "l"(p) : "memory");
}
__device__ __forceinline__ float sigf(float x) {
    return __fdividef(1.0f, 1.0f + __expf(-x));
}
__device__ __forceinline__ float tanhf_fast(float x) {
    return __fdividef(2.0f, 1.0f + __expf(-2.0f * x)) - 1.0f;
}

// ============ setup: pack weights/bias + transpose x + zero state ============
// blocks [0,96): pack; [96,96+TT): x transpose; then 3 blocks h slot0; 1 block flags
__global__ void setup_kernel(
    const float* __restrict__ x,
    const float* __restrict__ Wih0, const float* __restrict__ Whh0,
    const float* __restrict__ bih0, const float* __restrict__ bhh0,
    const float* __restrict__ Wih1, const float* __restrict__ Whh1,
    const float* __restrict__ bih1, const float* __restrict__ bhh1,
    const float* __restrict__ Wih2, const float* __restrict__ Whh2,
    const float* __restrict__ bih2, const float* __restrict__ bhh2)
{
    int blk = blockIdx.x, tid = threadIdx.x;
    if (blk < NL * GCTA) {
        int l = blk / GCTA, g = blk % GCTA;
        const float* Wih = (l == 0) ? Wih0 : ((l == 1) ? Wih1 : Wih2);
        const float* Whh = (l == 0) ? Whh0 : ((l == 1) ? Whh1 : Whh2);
        const float* bih = (l == 0) ? bih0 : ((l == 1) ? bih1 : bih2);
        const float* bhh = (l == 0) ? bhh0 : ((l == 1) ? bhh1 : bhh2);
        int KA = (l == 0) ? 8 : 128;
        int KP = KA + 128;
        int base = ((l == 0) ? WOFF0 : ((l == 1) ? WOFF1 : WOFF2)) + g * NR * KP;
        for (int idx = tid; idx < NR * KP; idx += blockDim.x) {
            int r = idx / KP, k = idx % KP;
            int q = r >> 2, jj = r & 3;
            int R = q * 128 + (g * NJ + jj);
            float v;
            if (k < KA) v = (l == 0) ? ((k < 6) ? Wih[R * 6 + k] : 0.0f)
                                     : Wih[R * 128 + k];
            else        v = Whh[R * 128 + (k - KA)];
            g_Wp[base + idx] = v;
        }
        if (tid < NR) {
            int r = tid, q = r >> 2, jj = r & 3;
            int R = q * 128 + (g * NJ + jj);
            g_bias[(l * GCTA + g) * NR + r] = bih[R] + bhh[R];
        }
    } else if (blk < NL * GCTA + TT) {
        int t = blk - NL * GCTA;
        if (tid < HB) {
            #pragma unroll
            for (int i = 0; i < 8; i++) {
                float v = (i < 6) ? x[(size_t)tid * (TT * 6) + t * 6 + i] : 0.0f;
                g_xT[(t * 8 + i) * HB + tid] = v;
            }
        }
    } else if (blk < NL * GCTA + TT + NL) {
        size_t base = (size_t)(blk - NL * GCTA - TT) * (TT + 1) * HB * HB;
        for (int i = tid; i < HB * HB; i += blockDim.x) g_H[base + i] = 0.0f;
    } else {
        for (int i = tid; i < NL * TT; i += blockDim.x) g_flags[i] = 0;
    }
}

// ---- GEMM slice, 2 batch cols per thread (b0 and b0+32), 16 packed cols.
// Source element for packed col k is src[k*HB + b] with src pre-shifted by caller.
template<int KP>
__device__ __forceinline__ void gemm16_2b(const float* __restrict__ src,
                                          const float* __restrict__ Wsm,
                                          int S, int b0, ull* acc /*32*/)
{
    #pragma unroll
    for (int kk = 0; kk < 16; kk += 4) {
        const float* sc = src + (S + kk) * HB + b0;
        float a0 = __ldcg(sc + 0 * HB);
        float a1 = __ldcg(sc + 1 * HB);
        float a2 = __ldcg(sc + 2 * HB);
        float a3 = __ldcg(sc + 3 * HB);
        float e0 = __ldcg(sc + 0 * HB + 32);
        float e1 = __ldcg(sc + 1 * HB + 32);
        float e2 = __ldcg(sc + 2 * HB + 32);
        float e3 = __ldcg(sc + 3 * HB + 32);
        ull h01 = pk2(a0, a1), h23 = pk2(a2, a3);
        ull g01 = pk2(e0, e1), g23 = pk2(e2, e3);
        const float* wrow = Wsm + S + kk;
        #pragma unroll
        for (int r = 0; r < NR; r++) {
            ulonglong2 w = *(const ulonglong2*)(wrow + r * KP); // LDS.128 bcast
            acc[r]      = ffma2(w.x, h01, acc[r]);
            acc[r]      = ffma2(w.y, h23, acc[r]);
            acc[NR + r] = ffma2(w.x, g01, acc[NR + r]);
            acc[NR + r] = ffma2(w.y, g23, acc[NR + r]);
        }
    }
}

// ---- 2-col slice (layer-0 input part), 2 batch cols per thread
template<int KP>
__device__ __forceinline__ void gemm2_2b(const float* __restrict__ src,
                                         const float* __restrict__ Wsm,
                                         int S, int b0, ull* acc)
{
    const float* sc = src + S * HB + b0;
    float a0 = __ldcg(sc + 0 * HB);
    float a1 = __ldcg(sc + 1 * HB);
    float e0 = __ldcg(sc + 0 * HB + 32);
    float e1 = __ldcg(sc + 1 * HB + 32);
    ull h01 = pk2(a0, a1), g01 = pk2(e0, e1);
    #pragma unroll
    for (int r = 0; r < NR; r++) {
        ull w = *(const ull*)(Wsm + S + r * KP);   // LDS.64 bcast
        acc[r]      = ffma2(w, h01, acc[r]);
        acc[NR + r] = ffma2(w, g01, acc[NR + r]);
    }
}

// ---- per-layer persistent body, 512 threads.
// GEMM: warp = kq*2+bg (kq = 1/8 K-slice, bg = 64-batch group); thread handles
// batches b0 = bg*64+lane and b0+32. Epilogue: thread owns (jj, be); carries c.
template<int L>
__device__ __forceinline__ void lstm_run(int g, float* Wsm, float* RD, float* bsm)
{
    constexpr int KA = (L == 0) ? 8 : 128;
    constexpr int KP = KA + 128;
    constexpr int WOFF = (L == 0) ? WOFF0 : ((L == 1) ? WOFF1 : WOFF2);

    const int tid  = threadIdx.x;
    const int lane = tid & 31;
    const int warp = tid >> 5;
    const int bg   = warp & 1;
    const int kq   = warp >> 1;          // 0..7
    const int b0   = bg * 64 + lane;
    const int jj   = tid >> 7;
    const int be   = tid & 127;
    const int jrow = g * NJ + jj;

    const int wbase = WOFF + g * NR * KP;
    for (int i = tid; i < NR * KP; i += 512) Wsm[i] = g_Wp[wbase + i];
    if (tid < NR) bsm[tid] = g_bias[(L * GCTA + g) * NR + tid];
    __syncthreads();

    float c = 0.0f;

    for (int t = 0; t < TT; t++) {
        // ---- phase A: input / below-layer contribution
        if (L > 0) {
            if (tid == 0) {
                const int* f = &g_flags[(L - 1) * TT + t];
                while (ldacq(f) < GCTA) {}
            }
            __syncthreads();
        }
        const float* SA = (L == 0)
            ? (g_xT + (size_t)t * 8 * HB)
            : (g_H + (size_t)((L - 1) * (TT + 1) + t + 1) * HB * HB);

        ull acc[2 * NR];
        #pragma unroll
        for (int r = 0; r < 2 * NR; r++) acc[r] = 0ULL;

        if constexpr (L == 0) {
            if (kq < 4) gemm2_2b<KP>(SA, Wsm, kq * 2, b0, acc);
        } else {
            gemm16_2b<KP>(SA, Wsm, kq * 16, b0, acc);
        }

        // ---- phase B: own h(t-1)
        if (tid == 0 && t > 0) {
            const int* f = &g_flags[L * TT + t - 1];
            while (ldacq(f) < GCTA) {}
        }
        __syncthreads();
        const float* SB = g_H + (size_t)(L * (TT + 1) + t) * HB * HB
                        - (size_t)KA * HB;   // pre-shift so packed col k works
        gemm16_2b<KP>(SB, Wsm, KA + kq * 16, b0, acc);

        #pragma unroll
        for (int r = 0; r < NR; r++) {
            float lo, hi; upk2(acc[r], lo, hi);
            RD[(kq * NR + r) * HB + b0] = lo + hi;
            upk2(acc[NR + r], lo, hi);
            RD[(kq * NR + r) * HB + b0 + 32] = lo + hi;
        }
        __syncthreads();

        // ---- epilogue: every thread one (jj, be)
        float v0 = bsm[0 * 4 + jj], v1 = bsm[1 * 4 + jj];
        float v2 = bsm[2 * 4 + jj], v3 = bsm[3 * 4 + jj];
        #pragma unroll
        for (int q2 = 0; q2 < 8; q2++) {
            v0 += RD[(q2 * NR + 0 * 4 + jj) * HB + be];
            v1 += RD[(q2 * NR + 1 * 4 + jj) * HB + be];
            v2 += RD[(q2 * NR + 2 * 4 + jj) * HB + be];
            v3 += RD[(q2 * NR + 3 * 4 + jj) * HB + be];
        }
        float iv = sigf(v0);
        float fv = sigf(v1);
        float gv = tanhf_fast(v2);
        float ov = sigf(v3);
        c = fv * c + iv * gv;
        float* Hout = g_H + (size_t)(L * (TT + 1) + t + 1) * HB * HB;
        __stcg(Hout + jrow * HB + be, ov * tanhf_fast(c));

        __syncthreads();   // all h stores program-ordered before the release
        if (tid == 0) red_release(&g_flags[L * TT + t]);
    }
}

__global__ void __launch_bounds__(512, 1) lstm_kernel(
    const float* __restrict__ W_out, const float* __restrict__ b_out,
    float* __restrict__ out)
{
    extern __shared__ float sm[];
    float* Wsm = sm;                       // NR*256 floats (16 KB)
    float* RD  = sm + NR * 256;            // 8*NR*HB floats (64 KB)
    float* bsm = RD + 8 * NR * HB;         // NR floats

    const int blk = blockIdx.x;
    const int l = blk >> 5, g = blk & 31;
    if (l == 0)      lstm_run<0>(g, Wsm, RD, bsm);
    else if (l == 1) lstm_run<1>(g, Wsm, RD, bsm);
    else             lstm_run<2>(g, Wsm, RD, bsm);

    // ---- head folded into one CTA: out[b] = h2[T-1][:,b] . W_out + b_out
    if (blk == 2 * GCTA) {
        if (threadIdx.x == 0) {
            const int* f = &g_flags[2 * TT + TT - 1];
            while (ldacq(f) < GCTA) {}
        }
        __syncthreads();
        if (threadIdx.x < HB) {
            const float* h = g_H + (size_t)(2 * (TT + 1) + TT) * HB * HB;
            float s = b_out[0];
            #pragma unroll 8
            for (int j = 0; j < HB; j++)
                s += __ldcg(h + j * HB + threadIdx.x) * W_out[j];
            out[threadIdx.x] = s;
        }
    }
}

extern "C" void kernel_launch(void* const* d_in, const int* in_sizes, int n_in,
                              void* d_out, int out_size)
{
    (void)in_sizes; (void)n_in; (void)out_size;

    const int SMEM_DYN = (NR * 256 + 8 * NR * HB + NR) * 4;   // 80,960 B
    cudaFuncSetAttribute(lstm_kernel,
                         cudaFuncAttributeMaxDynamicSharedMemorySize, SMEM_DYN);

    setup_kernel<<<NL * GCTA + TT + NL + 1, 256>>>(
        (const float*)d_in[0],
        (const float*)d_in[1], (const float*)d_in[2],
        (const float*)d_in[3], (const float*)d_in[4],
        (const float*)d_in[5], (const float*)d_in[6],
        (const float*)d_in[7], (const float*)d_in[8],
        (const float*)d_in[9], (const float*)d_in[10],
        (const float*)d_in[11], (const float*)d_in[12]);
    lstm_kernel<<<NL * GCTA, 512, SMEM_DYN>>>(
        (const float*)d_in[13], (const float*)d_in[14], (float*)d_out);
}